// round 6
// baseline (speedup 1.0000x reference)
#include <cuda_runtime.h>
#include <math.h>
#include <stdint.h>

#define TT 2048
#define DIMD 2048
#define NH 16
#define NKVH 4
#define HD 128
#define NQ (NH*HD)     // 2048
#define NKV (NKVH*HD)  // 512
#define REP (NH/NKVH)  // 4

// Scratch (device globals; allocation in kernel_launch is forbidden)
__device__ float g_q[TT*NQ];
__device__ float g_k[TT*NKV];
__device__ float g_v[TT*NKV];
__device__ float g_att[TT*NQ];
// tf32-rounded copies of GEMM inputs
__device__ float g_xr [TT*DIMD];
__device__ float g_wqr[NQ*DIMD];
__device__ float g_wkr[NKV*DIMD];
__device__ float g_wvr[NKV*DIMD];
__device__ float g_wor[DIMD*NQ];

// ---------------------------------------------------------------------------
// helpers
// ---------------------------------------------------------------------------
__device__ __forceinline__ unsigned f2tf(float f) {
    unsigned u; asm("cvt.rna.tf32.f32 %0, %1;" : "=r"(u) : "f"(f)); return u;
}

// Fused tf32 rounding of all 5 GEMM inputs in one launch (segmented).
// Segment boundaries in float4 units.
#define R_X   (TT*DIMD/4)          // 1048576
#define R_WQ  (NQ*DIMD/4)          // 1048576
#define R_WKV (NKV*DIMD/4)         // 262144
#define R_TOT (R_X + R_WQ + 2*R_WKV + NQ*DIMD/4)

__global__ void round_all_kernel(const float* __restrict__ x,
                                 const float* __restrict__ wq,
                                 const float* __restrict__ wk,
                                 const float* __restrict__ wv,
                                 const float* __restrict__ wo,
                                 float* __restrict__ xr,
                                 float* __restrict__ wqr,
                                 float* __restrict__ wkr,
                                 float* __restrict__ wvr,
                                 float* __restrict__ wor)
{
    int i = blockIdx.x * blockDim.x + threadIdx.x;
    if (i >= R_TOT) return;
    const float* in; float* out; int j = i;
    if (j < R_X)               { in = x;  out = xr;  }
    else if ((j -= R_X)   < R_WQ)  { in = wq; out = wqr; }
    else if ((j -= R_WQ)  < R_WKV) { in = wk; out = wkr; }
    else if ((j -= R_WKV) < R_WKV) { in = wv; out = wvr; }
    else { j -= R_WKV;           in = wo; out = wor; }
    float4 v = ((const float4*)in)[j];
    uint4 o;
    o.x = f2tf(v.x); o.y = f2tf(v.y); o.z = f2tf(v.z); o.w = f2tf(v.w);
    ((uint4*)out)[j] = o;
}

__device__ __forceinline__ void cp_async16(unsigned saddr, const void* g) {
    asm volatile("cp.async.cg.shared.global [%0], [%1], 16;\n"
                 :: "r"(saddr), "l"(g));
}
__device__ __forceinline__ void cp_commit() {
    asm volatile("cp.async.commit_group;\n");
}
__device__ __forceinline__ void cp_wait0() {
    asm volatile("cp.async.wait_group 0;\n");
}
__device__ __forceinline__ void cp_wait1() {
    asm volatile("cp.async.wait_group 1;\n");
}

__device__ __forceinline__ void mma_tf32(float c[4], const uint4& a,
                                         unsigned b0, unsigned b1) {
    asm volatile(
        "mma.sync.aligned.m16n8k8.row.col.f32.tf32.tf32.f32 "
        "{%0,%1,%2,%3}, {%4,%5,%6,%7}, {%8,%9}, {%0,%1,%2,%3};\n"
        : "+f"(c[0]), "+f"(c[1]), "+f"(c[2]), "+f"(c[3])
        : "r"(a.x), "r"(a.y), "r"(a.z), "r"(a.w), "r"(b0), "r"(b1));
}

__device__ __forceinline__ void ldsm_x4(uint4& d, unsigned addr) {
    asm volatile(
        "ldmatrix.sync.aligned.m8n8.x4.shared.b16 {%0,%1,%2,%3}, [%4];\n"
        : "=r"(d.x), "=r"(d.y), "=r"(d.z), "=r"(d.w) : "r"(addr));
}

// ---------------------------------------------------------------------------
// Tensor-core tf32 GEMM: C[M,N] = A[M,K] * B[N,K]^T, A/B pre-rounded to tf32.
// 128x128 tile, BK=32, 256 threads (8 warps, 4x2), warp tile 32x64.
// Fragments loaded via ldmatrix (conflict-free with stride 36).
// ---------------------------------------------------------------------------
#define BM 128
#define BN 128
#define BKK 32
#define SAST 36
#define GEMM_ASZ (BM*SAST)
#define GEMM_STAGE (2*GEMM_ASZ)
#define GEMM_SMEM (2*GEMM_STAGE*4)

__device__ __forceinline__ void gemm_tc(
    const float* __restrict__ A, const float* __restrict__ B,
    float* __restrict__ C, int N, int K, int bm, int bn, int round_out)
{
    extern __shared__ float smf[];
    int tid = threadIdx.x;
    int lane = tid & 31, wid = tid >> 5;
    int wm = (wid & 3) * 32;
    int wn = (wid >> 2) * 64;
    int g = lane >> 2, t = lane & 3;

    int lrow = lane & 7;
    int am   = lane >> 3;
    int a_row  = wm + ((am & 1) << 3) + lrow;
    int a_col4 = (am >> 1) << 2;
    int b_row  = wn + ((am >> 1) << 3) + lrow;
    int b_col4 = (am & 1) << 2;

    unsigned smem_base = (unsigned)__cvta_generic_to_shared(smf);

    float c[2][8][4];
#pragma unroll
    for (int mi = 0; mi < 2; mi++)
#pragma unroll
        for (int nj = 0; nj < 8; nj++)
#pragma unroll
            for (int r = 0; r < 4; r++) c[mi][nj][r] = 0.f;

    const int KT = K / BKK;

    auto load_stage = [&](int s, int kt) {
        int k0 = kt * BKK;
        unsigned sa = smem_base + (unsigned)(s * GEMM_STAGE) * 4u;
        unsigned sb = sa + (unsigned)GEMM_ASZ * 4u;
#pragma unroll
        for (int i = 0; i < 4; i++) {
            int idx = tid + 256 * i;
            int row = idx >> 3;
            int kc  = (idx & 7) * 4;
            cp_async16(sa + (unsigned)(row * SAST + kc) * 4u,
                       &A[(size_t)(bm + row) * K + k0 + kc]);
            cp_async16(sb + (unsigned)(row * SAST + kc) * 4u,
                       &B[(size_t)(bn + row) * K + k0 + kc]);
        }
        cp_commit();
    };

    load_stage(0, 0);

    for (int kt = 0; kt < KT; kt++) {
        if (kt + 1 < KT) { load_stage((kt + 1) & 1, kt + 1); cp_wait1(); }
        else             { cp_wait0(); }
        __syncthreads();

        unsigned sA = smem_base + (unsigned)((kt & 1) * GEMM_STAGE) * 4u;
        unsigned sB = sA + (unsigned)GEMM_ASZ * 4u;

#pragma unroll
        for (int ks = 0; ks < 4; ks++) {
            int k0 = ks * 8;
            uint4 a[2], bp[4];
#pragma unroll
            for (int mi = 0; mi < 2; mi++)
                ldsm_x4(a[mi], sA + (unsigned)((a_row + mi*16) * SAST
                                               + k0 + a_col4) * 4u);
#pragma unroll
            for (int p = 0; p < 4; p++)
                ldsm_x4(bp[p], sB + (unsigned)((b_row + p*16) * SAST
                                               + k0 + b_col4) * 4u);
#pragma unroll
            for (int mi = 0; mi < 2; mi++)
#pragma unroll
                for (int p = 0; p < 4; p++) {
                    mma_tf32(c[mi][2*p  ], a[mi], bp[p].x, bp[p].y);
                    mma_tf32(c[mi][2*p+1], a[mi], bp[p].z, bp[p].w);
                }
        }
        __syncthreads();
    }

#pragma unroll
    for (int mi = 0; mi < 2; mi++) {
#pragma unroll
        for (int nj = 0; nj < 8; nj++) {
            int row0 = bm + wm + mi * 16 + g;
            int col  = bn + wn + nj * 8 + 2 * t;
            float v0 = c[mi][nj][0], v1 = c[mi][nj][1];
            float v2 = c[mi][nj][2], v3 = c[mi][nj][3];
            if (round_out) {
                v0 = __uint_as_float(f2tf(v0)); v1 = __uint_as_float(f2tf(v1));
                v2 = __uint_as_float(f2tf(v2)); v3 = __uint_as_float(f2tf(v3));
            }
            *(float2*)&C[(size_t)row0 * N + col]       = make_float2(v0, v1);
            *(float2*)&C[(size_t)(row0 + 8) * N + col] = make_float2(v2, v3);
        }
    }
}

// Fused Q/K/V projections: grid.x = 16 (Q) + 4 (K) + 4 (V), grid.y = 16.
__global__ __launch_bounds__(256, 2) void qkv_gemm_kernel(
    const float* __restrict__ A,
    const float* __restrict__ Bq, const float* __restrict__ Bk,
    const float* __restrict__ Bv,
    float* __restrict__ Cq, float* __restrict__ Ck, float* __restrict__ Cv)
{
    int bx = blockIdx.x, bm = blockIdx.y * BM;
    if (bx < 16)      gemm_tc(A, Bq, Cq, NQ,  DIMD, bm, bx * BN, 0);
    else if (bx < 20) gemm_tc(A, Bk, Ck, NKV, DIMD, bm, (bx-16) * BN, 0);
    else              gemm_tc(A, Bv, Cv, NKV, DIMD, bm, (bx-20) * BN, 1);
}

__global__ __launch_bounds__(256, 2) void gemm_tc_kernel(
    const float* __restrict__ A, const float* __restrict__ B,
    float* __restrict__ C, int N, int K)
{
    gemm_tc(A, B, C, N, K, blockIdx.y * BM, blockIdx.x * BN, 0);
}

// ---------------------------------------------------------------------------
// Fused RoPE over Q (16 heads, scaled) and K (4 heads): one launch.
// Virtual head hh in [0,20): hh<16 -> Q head hh; else K head hh-16.
// ---------------------------------------------------------------------------
__global__ void rope_fused_kernel(float* __restrict__ q, float* __restrict__ k,
                                  const float* __restrict__ cs,
                                  const float* __restrict__ sn, float qscale)
{
    int idx = blockIdx.x * blockDim.x + threadIdx.x;  // TT*20*64 threads
    int i  = idx & 63;
    int hh = (idx >> 6) % 20;
    int t  = idx / (64 * 20);
    if (t >= TT) return;
    float c = cs[t * HD + i];
    float s = sn[t * HD + i];
    float* p;
    float scale;
    if (hh < NH) { p = q + ((size_t)t * NH   + hh)        * HD; scale = qscale; }
    else         { p = k + ((size_t)t * NKVH + (hh - NH)) * HD; scale = 1.0f;  }
    float u1 = p[i], u2 = p[i + 64];
    p[i]      = __uint_as_float(f2tf((u1 * c - u2 * s) * scale));
    p[i + 64] = __uint_as_float(f2tf((u2 * c + u1 * s) * scale));
}

// ---------------------------------------------------------------------------
// Tensor-core flash attention (tf32, legacy mma). BQ=128, BKV=64, 256 thr.
// PERSISTENT + SNAKE: 128 CTAs, CTA b processes items r=b and r=255-b.
// Item r: qb = 15 - (r>>4) (heavy first), h = r & 15. Weight(qb)=qb+1, so
// every CTA gets exactly 17 weight units -> perfectly balanced single wave.
// ---------------------------------------------------------------------------
#define FAQ 128
#define FA_QST 132
#define FA_VST 136
#define FA_QSZ (FAQ*FA_QST)
#define FA_KSZ (64*FA_QST)
#define FA_KVSZ (FA_KSZ + 64*FA_VST)
#define FA_SMEM ((FA_QSZ + 2*FA_KVSZ)*4)
#define FA_ITEMS (NH * (TT/FAQ))   // 256

__global__ __launch_bounds__(256, 1) void fa_tc_kernel(float* __restrict__ att)
{
    extern __shared__ float smf[];
    int tid = threadIdx.x;
    int lane = tid & 31, wid = tid >> 5;
    int g = lane >> 2, t = lane & 3;
    int w16 = wid * 16;

    int lrow = lane & 7;
    int am   = lane >> 3;
    int a_row  = w16 + ((am & 1) << 3) + lrow;
    int a_col4 = (am >> 1) << 2;
    int b_row  = ((am >> 1) << 3) + lrow;
    int b_col4 = (am & 1) << 2;

    unsigned smem_base = (unsigned)__cvta_generic_to_shared(smf);
    float* Qs = smf;

#pragma unroll 1
    for (int pass = 0; pass < 2; pass++) {
        int r = pass == 0 ? (int)blockIdx.x : (FA_ITEMS - 1 - (int)blockIdx.x);
        int qb = (TT/FAQ) - 1 - (r >> 4);
        int h  = r & 15;
        int g0 = h / REP;

        // Load Q tile (pre-rounded tf32)
#pragma unroll
        for (int i = 0; i < 16; i++) {
            int idx = tid + 256 * i;
            int rr = idx >> 5;
            int c4 = (idx & 31) * 4;
            *(float4*)&Qs[rr*FA_QST + c4] =
                *(const float4*)&g_q[(size_t)(qb*FAQ + rr) * NQ + h*HD + c4];
        }

        auto load_kv = [&](int kb, int s) {
            const float* Kg = &g_k[(size_t)(kb*64) * NKV + g0*HD];
            const float* Vg = &g_v[(size_t)(kb*64) * NKV + g0*HD];
            unsigned kbase = smem_base + (unsigned)(FA_QSZ + s*FA_KVSZ) * 4u;
            unsigned vbase = kbase + (unsigned)FA_KSZ * 4u;
#pragma unroll
            for (int i = 0; i < 8; i++) {
                int idx = tid + 256 * i;
                int rr = idx >> 5;
                int c4 = (idx & 31) * 4;
                cp_async16(kbase + (unsigned)(rr*FA_QST + c4) * 4u,
                           Kg + (size_t)rr*NKV + c4);
                cp_async16(vbase + (unsigned)(rr*FA_VST + c4) * 4u,
                           Vg + (size_t)rr*NKV + c4);
            }
            cp_commit();
        };

        float o[16][4];
#pragma unroll
        for (int nj = 0; nj < 16; nj++)
#pragma unroll
            for (int rr = 0; rr < 4; rr++) o[nj][rr] = 0.f;
        float m0 = -1e30f, m1 = -1e30f, l0 = 0.f, l1 = 0.f;

        const int kb_max = 2*qb + 1;
        // Q tile written with plain STS; sync before first K/V consume is
        // covered by the __syncthreads below (after cp_wait).
        load_kv(0, 0);

        for (int kb = 0; kb <= kb_max; kb++) {
            if (kb < kb_max) { load_kv(kb + 1, (kb + 1) & 1); cp_wait1(); }
            else             { cp_wait0(); }
            __syncthreads();

            unsigned sK = smem_base + (unsigned)(FA_QSZ + (kb & 1)*FA_KVSZ) * 4u;
            const float* Vs = smf + FA_QSZ + (kb & 1)*FA_KVSZ + FA_KSZ;

            float s[8][4];
#pragma unroll
            for (int nj = 0; nj < 8; nj++)
#pragma unroll
                for (int rr = 0; rr < 4; rr++) s[nj][rr] = 0.f;

#pragma unroll
            for (int ks = 0; ks < 16; ks++) {
                int k0 = ks * 8;
                uint4 a, bp[4];
                ldsm_x4(a, smem_base + (unsigned)(a_row*FA_QST + k0 + a_col4)*4u);
#pragma unroll
                for (int p = 0; p < 4; p++)
                    ldsm_x4(bp[p], sK + (unsigned)((b_row + p*16)*FA_QST
                                                   + k0 + b_col4)*4u);
#pragma unroll
                for (int p = 0; p < 4; p++) {
                    mma_tf32(s[2*p  ], a, bp[p].x, bp[p].y);
                    mma_tf32(s[2*p+1], a, bp[p].z, bp[p].w);
                }
            }

            if (kb >= 2*qb) {
                int r0 = qb*FAQ + w16 + g, r1 = r0 + 8;
                int cb0 = kb*64 + 2*t;
#pragma unroll
                for (int nj = 0; nj < 8; nj++) {
                    int c0 = cb0 + nj*8, c1 = c0 + 1;
                    if (c0 > r0) s[nj][0] = -1e30f;
                    if (c1 > r0) s[nj][1] = -1e30f;
                    if (c0 > r1) s[nj][2] = -1e30f;
                    if (c1 > r1) s[nj][3] = -1e30f;
                }
            }

            float mx0 = -1e30f, mx1 = -1e30f;
#pragma unroll
            for (int nj = 0; nj < 8; nj++) {
                mx0 = fmaxf(mx0, fmaxf(s[nj][0], s[nj][1]));
                mx1 = fmaxf(mx1, fmaxf(s[nj][2], s[nj][3]));
            }
            mx0 = fmaxf(mx0, __shfl_xor_sync(0xffffffffu, mx0, 1));
            mx0 = fmaxf(mx0, __shfl_xor_sync(0xffffffffu, mx0, 2));
            mx1 = fmaxf(mx1, __shfl_xor_sync(0xffffffffu, mx1, 1));
            mx1 = fmaxf(mx1, __shfl_xor_sync(0xffffffffu, mx1, 2));
            float mn0 = fmaxf(m0, mx0), mn1 = fmaxf(m1, mx1);
            float al0 = __expf(m0 - mn0), al1 = __expf(m1 - mn1);
            m0 = mn0; m1 = mn1;

            float rs0 = 0.f, rs1 = 0.f;
#pragma unroll
            for (int nj = 0; nj < 8; nj++) {
                s[nj][0] = __expf(s[nj][0] - mn0);
                s[nj][1] = __expf(s[nj][1] - mn0);
                s[nj][2] = __expf(s[nj][2] - mn1);
                s[nj][3] = __expf(s[nj][3] - mn1);
                rs0 += s[nj][0] + s[nj][1];
                rs1 += s[nj][2] + s[nj][3];
            }
            rs0 += __shfl_xor_sync(0xffffffffu, rs0, 1);
            rs0 += __shfl_xor_sync(0xffffffffu, rs0, 2);
            rs1 += __shfl_xor_sync(0xffffffffu, rs1, 1);
            rs1 += __shfl_xor_sync(0xffffffffu, rs1, 2);
            l0 = l0 * al0 + rs0;
            l1 = l1 * al1 + rs1;

#pragma unroll
            for (int nj = 0; nj < 16; nj++) {
                o[nj][0] *= al0; o[nj][1] *= al0;
                o[nj][2] *= al1; o[nj][3] *= al1;
            }

            int src0 = (lane & ~3) + (t >> 1);
            int src1 = src0 + 2;
#pragma unroll
            for (int kt = 0; kt < 8; kt++) {
                float p00 = __shfl_sync(0xffffffffu, s[kt][0], src0);
                float p01 = __shfl_sync(0xffffffffu, s[kt][1], src0);
                float p20 = __shfl_sync(0xffffffffu, s[kt][2], src0);
                float p21 = __shfl_sync(0xffffffffu, s[kt][3], src0);
                float q00 = __shfl_sync(0xffffffffu, s[kt][0], src1);
                float q01 = __shfl_sync(0xffffffffu, s[kt][1], src1);
                float q20 = __shfl_sync(0xffffffffu, s[kt][2], src1);
                float q21 = __shfl_sync(0xffffffffu, s[kt][3], src1);
                uint4 a;
                a.x = f2tf((t & 1) ? p01 : p00);
                a.y = f2tf((t & 1) ? p21 : p20);
                a.z = f2tf((t & 1) ? q01 : q00);
                a.w = f2tf((t & 1) ? q21 : q20);
#pragma unroll
                for (int nj = 0; nj < 16; nj++) {
                    unsigned b0 = __float_as_uint(Vs[(kt*8 + t    )*FA_VST + nj*8 + g]);
                    unsigned b1 = __float_as_uint(Vs[(kt*8 + t + 4)*FA_VST + nj*8 + g]);
                    mma_tf32(o[nj], a, b0, b1);
                }
            }
            __syncthreads();
        }

        float il0 = 1.0f / l0, il1 = 1.0f / l1;
#pragma unroll
        for (int nj = 0; nj < 16; nj++) {
            int row0 = qb*FAQ + w16 + g;
            int col  = h*HD + nj*8 + 2*t;
            float2 v0 = make_float2(__uint_as_float(f2tf(o[nj][0]*il0)),
                                    __uint_as_float(f2tf(o[nj][1]*il0)));
            float2 v1 = make_float2(__uint_as_float(f2tf(o[nj][2]*il1)),
                                    __uint_as_float(f2tf(o[nj][3]*il1)));
            *(float2*)&att[(size_t)row0 * NQ + col]       = v0;
            *(float2*)&att[(size_t)(row0 + 8) * NQ + col] = v1;
        }
        // Qs is overwritten next pass; last __syncthreads above covers all
        // smem readers of this pass.
    }
}

// ---------------------------------------------------------------------------
extern "C" void kernel_launch(void* const* d_in, const int* in_sizes, int n_in,
                              void* d_out, int out_size)
{
    const float* x  = (const float*)d_in[0];
    const float* wq = (const float*)d_in[1];
    const float* wk = (const float*)d_in[2];
    const float* wv = (const float*)d_in[3];
    const float* wo = (const float*)d_in[4];
    const float* cs = (const float*)d_in[5];
    const float* sn = (const float*)d_in[6];
    float* out = (float*)d_out;

    float *q, *k, *v, *att, *xr, *wqr, *wkr, *wvr, *wor;
    cudaGetSymbolAddress((void**)&q,   g_q);
    cudaGetSymbolAddress((void**)&k,   g_k);
    cudaGetSymbolAddress((void**)&v,   g_v);
    cudaGetSymbolAddress((void**)&att, g_att);
    cudaGetSymbolAddress((void**)&xr,  g_xr);
    cudaGetSymbolAddress((void**)&wqr, g_wqr);
    cudaGetSymbolAddress((void**)&wkr, g_wkr);
    cudaGetSymbolAddress((void**)&wvr, g_wvr);
    cudaGetSymbolAddress((void**)&wor, g_wor);

    static bool attr_set = false;
    if (!attr_set) {
        cudaFuncSetAttribute(qkv_gemm_kernel,
            cudaFuncAttributeMaxDynamicSharedMemorySize, GEMM_SMEM);
        cudaFuncSetAttribute(gemm_tc_kernel,
            cudaFuncAttributeMaxDynamicSharedMemorySize, GEMM_SMEM);
        cudaFuncSetAttribute(fa_tc_kernel,
            cudaFuncAttributeMaxDynamicSharedMemorySize, FA_SMEM);
        attr_set = true;
    }

    // Pre-round all GEMM inputs to tf32 in ONE launch
    round_all_kernel<<<(R_TOT + 255)/256, 256>>>(
        x, wq, wk, wv, wo, xr, wqr, wkr, wvr, wor);

    // Fused QKV projection (V output rounded to tf32 for FA)
    qkv_gemm_kernel<<<dim3(24, TT/BM), 256, GEMM_SMEM>>>(
        xr, wqr, wkr, wvr, q, k, v);

    // Fused RoPE over Q and K (rounds to tf32; Q gets 1/sqrt(HD) folded in)
    const float scale = 0.08838834764831845f;  // 128^-0.5
    rope_fused_kernel<<<(TT*20*64)/256, 256>>>(q, k, cs, sn, scale);

    // Tensor-core flash attention: 128 persistent CTAs, snake-balanced
    fa_tc_kernel<<<dim3(FA_ITEMS/2, 1), 256, FA_SMEM>>>(att);

    // Output projection
    gemm_tc_kernel<<<dim3(DIMD/BN, TT/BM), 256, GEMM_SMEM>>>(
        att, wor, out, NQ, NQ);
}

// round 7
// speedup vs baseline: 1.0037x; 1.0037x over previous
#include <cuda_runtime.h>
#include <math.h>
#include <stdint.h>

#define TT 2048
#define DIMD 2048
#define NH 16
#define NKVH 4
#define HD 128
#define NQ (NH*HD)     // 2048
#define NKV (NKVH*HD)  // 512
#define REP (NH/NKVH)  // 4
#define QKVW 3072      // packed qkv width

// Scratch (device globals; allocation in kernel_launch is forbidden)
__device__ float g_qkv[TT*QKVW];     // [T][3072]: Q | K | V
__device__ float g_att[TT*NQ];
__device__ float g_xr  [TT*DIMD];
__device__ float g_wqkv[QKVW*DIMD];  // rows: wq(2048) | wk(512) | wv(512)
__device__ float g_wor [DIMD*NQ];

// ---------------------------------------------------------------------------
// helpers
// ---------------------------------------------------------------------------
__device__ __forceinline__ unsigned f2tf(float f) {
    unsigned u; asm("cvt.rna.tf32.f32 %0, %1;" : "=r"(u) : "f"(f)); return u;
}

#define R_X   (TT*DIMD/4)
#define R_WQ  (NQ*DIMD/4)
#define R_WKV (NKV*DIMD/4)
#define R_TOT (R_X + R_WQ + 2*R_WKV + NQ*DIMD/4)

__global__ void round_all_kernel(const float* __restrict__ x,
                                 const float* __restrict__ wq,
                                 const float* __restrict__ wk,
                                 const float* __restrict__ wv,
                                 const float* __restrict__ wo,
                                 float* __restrict__ xr,
                                 float* __restrict__ wqkv,
                                 float* __restrict__ wor)
{
    int i = blockIdx.x * blockDim.x + threadIdx.x;
    if (i >= R_TOT) return;
    const float* in; float* out; int j = i;
    if (j < R_X)                   { in = x;  out = xr; }
    else if ((j -= R_X)   < R_WQ)  { in = wq; out = wqkv; }
    else if ((j -= R_WQ)  < R_WKV) { in = wk; out = wqkv + (size_t)NQ*DIMD; }
    else if ((j -= R_WKV) < R_WKV) { in = wv; out = wqkv + (size_t)(NQ+NKV)*DIMD; }
    else { j -= R_WKV;               in = wo; out = wor; }
    float4 v = ((const float4*)in)[j];
    uint4 o;
    o.x = f2tf(v.x); o.y = f2tf(v.y); o.z = f2tf(v.z); o.w = f2tf(v.w);
    ((uint4*)out)[j] = o;
}

__device__ __forceinline__ void cp_async16(unsigned saddr, const void* g) {
    asm volatile("cp.async.cg.shared.global [%0], [%1], 16;\n"
                 :: "r"(saddr), "l"(g));
}
__device__ __forceinline__ void cp_commit() {
    asm volatile("cp.async.commit_group;\n");
}
__device__ __forceinline__ void cp_wait0() {
    asm volatile("cp.async.wait_group 0;\n");
}
__device__ __forceinline__ void cp_wait1() {
    asm volatile("cp.async.wait_group 1;\n");
}

__device__ __forceinline__ void mma_tf32(float c[4], const uint4& a,
                                         unsigned b0, unsigned b1) {
    asm volatile(
        "mma.sync.aligned.m16n8k8.row.col.f32.tf32.tf32.f32 "
        "{%0,%1,%2,%3}, {%4,%5,%6,%7}, {%8,%9}, {%0,%1,%2,%3};\n"
        : "+f"(c[0]), "+f"(c[1]), "+f"(c[2]), "+f"(c[3])
        : "r"(a.x), "r"(a.y), "r"(a.z), "r"(a.w), "r"(b0), "r"(b1));
}

__device__ __forceinline__ void ldsm_x4(uint4& d, unsigned addr) {
    asm volatile(
        "ldmatrix.sync.aligned.m8n8.x4.shared.b16 {%0,%1,%2,%3}, [%4];\n"
        : "=r"(d.x), "=r"(d.y), "=r"(d.z), "=r"(d.w) : "r"(addr));
}

// ---------------------------------------------------------------------------
// Tensor-core tf32 GEMM: C[2048,N] = A[2048,2048] * B[N,2048]^T.
// CTA tile 128 x NT, 256 threads (8 warps as 2m x 4n), warp tile 64 x (NT/4).
// BK=32, 2-stage cp.async, ldmatrix fragments (stride 36 conflict-free).
// Columns >= rt_col are rounded to tf32 on output.
// ---------------------------------------------------------------------------
#define BKK 32
#define SAST 36
#define GK 2048

template <int NT>
__device__ __forceinline__ void gemm_tc(
    const float* __restrict__ A, const float* __restrict__ B,
    float* __restrict__ C, int N, int bm, int bn, int rt_col)
{
    constexpr int WN  = NT / 4;          // warp n width (96 or 64)
    constexpr int PB  = WN / 16;         // b ldsm per ks (6 or 4)
    constexpr int PBH = PB / 2;          // per half (3 or 2)
    constexpr int ASZ = 128 * SAST;
    constexpr int BSZ = NT * SAST;
    constexpr int STG = ASZ + BSZ;

    extern __shared__ float smf[];
    int tid = threadIdx.x;
    int lane = tid & 31, wid = tid >> 5;
    int wm = (wid & 1) * 64;
    int wn = (wid >> 1) * WN;
    int g = lane >> 2, t = lane & 3;

    int lrow = lane & 7;
    int am   = lane >> 3;
    int a_row  = wm + ((am & 1) << 3) + lrow;
    int a_col4 = (am >> 1) << 2;
    int b_row  = wn + ((am >> 1) << 3) + lrow;
    int b_col4 = (am & 1) << 2;

    unsigned smem_base = (unsigned)__cvta_generic_to_shared(smf);

    float c[4][2*PB][4];
#pragma unroll
    for (int mi = 0; mi < 4; mi++)
#pragma unroll
        for (int nj = 0; nj < 2*PB; nj++)
#pragma unroll
            for (int r = 0; r < 4; r++) c[mi][nj][r] = 0.f;

    auto load_stage = [&](int s, int kt) {
        int k0 = kt * BKK;
        unsigned sa = smem_base + (unsigned)(s * STG) * 4u;
        unsigned sb = sa + (unsigned)ASZ * 4u;
#pragma unroll
        for (int i = 0; i < 4; i++) {                 // A: 128x32
            int idx = tid + 256 * i;
            int row = idx >> 3;
            int kc  = (idx & 7) * 4;
            cp_async16(sa + (unsigned)(row * SAST + kc) * 4u,
                       &A[(size_t)(bm + row) * GK + k0 + kc]);
        }
#pragma unroll
        for (int i = 0; i < NT/32; i++) {             // B: NTx32
            int idx = tid + 256 * i;
            int row = idx >> 3;
            int kc  = (idx & 7) * 4;
            cp_async16(sb + (unsigned)(row * SAST + kc) * 4u,
                       &B[(size_t)(bn + row) * GK + k0 + kc]);
        }
        cp_commit();
    };

    load_stage(0, 0);
    const int KT = GK / BKK;

    for (int kt = 0; kt < KT; kt++) {
        if (kt + 1 < KT) { load_stage((kt + 1) & 1, kt + 1); cp_wait1(); }
        else             { cp_wait0(); }
        __syncthreads();

        unsigned sA = smem_base + (unsigned)((kt & 1) * STG) * 4u;
        unsigned sB = sA + (unsigned)ASZ * 4u;

#pragma unroll
        for (int ks = 0; ks < 4; ks++) {
            int k0 = ks * 8;
            uint4 a[4];
#pragma unroll
            for (int mi = 0; mi < 4; mi++)
                ldsm_x4(a[mi], sA + (unsigned)((a_row + mi*16) * SAST
                                               + k0 + a_col4) * 4u);
#pragma unroll
            for (int ph = 0; ph < 2; ph++) {
                uint4 bp[PBH];
#pragma unroll
                for (int p2 = 0; p2 < PBH; p2++)
                    ldsm_x4(bp[p2],
                        sB + (unsigned)((b_row + (ph*PBH + p2)*16) * SAST
                                        + k0 + b_col4) * 4u);
#pragma unroll
                for (int mi = 0; mi < 4; mi++)
#pragma unroll
                    for (int p2 = 0; p2 < PBH; p2++) {
                        int p = ph*PBH + p2;
                        mma_tf32(c[mi][2*p  ], a[mi], bp[p2].x, bp[p2].y);
                        mma_tf32(c[mi][2*p+1], a[mi], bp[p2].z, bp[p2].w);
                    }
            }
        }
        __syncthreads();
    }

#pragma unroll
    for (int mi = 0; mi < 4; mi++) {
#pragma unroll
        for (int nj = 0; nj < 2*PB; nj++) {
            int row0 = bm + wm + mi * 16 + g;
            int col  = bn + wn + nj * 8 + 2 * t;
            float v0 = c[mi][nj][0], v1 = c[mi][nj][1];
            float v2 = c[mi][nj][2], v3 = c[mi][nj][3];
            if (col >= rt_col) {
                v0 = __uint_as_float(f2tf(v0)); v1 = __uint_as_float(f2tf(v1));
                v2 = __uint_as_float(f2tf(v2)); v3 = __uint_as_float(f2tf(v3));
            }
            *(float2*)&C[(size_t)row0 * N + col]       = make_float2(v0, v1);
            *(float2*)&C[(size_t)(row0 + 8) * N + col] = make_float2(v2, v3);
        }
    }
}

#define QKV_SMEM (2*(128+384)*SAST*4)
#define OPJ_SMEM (2*(128+256)*SAST*4)

// Packed QKV projection: grid (8, 16). V columns (>=2560) rounded to tf32.
__global__ __launch_bounds__(256, 1) void qkv_gemm_kernel(
    const float* __restrict__ A, const float* __restrict__ B,
    float* __restrict__ C)
{
    gemm_tc<384>(A, B, C, QKVW, blockIdx.y * 128, blockIdx.x * 384,
                 NQ + NKV /* 2560 */);
}

// Output projection: grid (8, 16).
__global__ __launch_bounds__(256, 1) void oproj_gemm_kernel(
    const float* __restrict__ A, const float* __restrict__ B,
    float* __restrict__ C)
{
    gemm_tc<256>(A, B, C, DIMD, blockIdx.y * 128, blockIdx.x * 256,
                 0x40000000);
}

// ---------------------------------------------------------------------------
// Fused RoPE over Q (16 heads, scaled) and K (4 heads) in packed g_qkv.
// ---------------------------------------------------------------------------
__global__ void rope_fused_kernel(float* __restrict__ qkv,
                                  const float* __restrict__ cs,
                                  const float* __restrict__ sn, float qscale)
{
    int idx = blockIdx.x * blockDim.x + threadIdx.x;  // TT*20*64 threads
    int i  = idx & 63;
    int hh = (idx >> 6) % 20;
    int t  = idx / (64 * 20);
    if (t >= TT) return;
    float c = cs[t * HD + i];
    float s = sn[t * HD + i];
    float* p;
    float scale;
    if (hh < NH) { p = qkv + (size_t)t * QKVW + hh * HD;            scale = qscale; }
    else         { p = qkv + (size_t)t * QKVW + NQ + (hh - NH) * HD; scale = 1.0f; }
    float u1 = p[i], u2 = p[i + 64];
    p[i]      = __uint_as_float(f2tf((u1 * c - u2 * s) * scale));
    p[i + 64] = __uint_as_float(f2tf((u2 * c + u1 * s) * scale));
}

// ---------------------------------------------------------------------------
// Tensor-core flash attention (tf32, legacy mma). BQ=128, BKV=64, 256 thr.
// Persistent snake: 128 CTAs, CTA b handles items b and 255-b (balanced).
// Reads Q/K/V from packed g_qkv (stride 3072).
// ---------------------------------------------------------------------------
#define FAQ 128
#define FA_QST 132
#define FA_VST 136
#define FA_QSZ (FAQ*FA_QST)
#define FA_KSZ (64*FA_QST)
#define FA_KVSZ (FA_KSZ + 64*FA_VST)
#define FA_SMEM ((FA_QSZ + 2*FA_KVSZ)*4)
#define FA_ITEMS (NH * (TT/FAQ))   // 256

__global__ __launch_bounds__(256, 1) void fa_tc_kernel(float* __restrict__ att)
{
    extern __shared__ float smf[];
    int tid = threadIdx.x;
    int lane = tid & 31, wid = tid >> 5;
    int g = lane >> 2, t = lane & 3;
    int w16 = wid * 16;

    int lrow = lane & 7;
    int am   = lane >> 3;
    int a_row  = w16 + ((am & 1) << 3) + lrow;
    int a_col4 = (am >> 1) << 2;
    int b_row  = ((am >> 1) << 3) + lrow;
    int b_col4 = (am & 1) << 2;

    unsigned smem_base = (unsigned)__cvta_generic_to_shared(smf);
    float* Qs = smf;

#pragma unroll 1
    for (int pass = 0; pass < 2; pass++) {
        int r = pass == 0 ? (int)blockIdx.x : (FA_ITEMS - 1 - (int)blockIdx.x);
        int qb = (TT/FAQ) - 1 - (r >> 4);
        int h  = r & 15;
        int g0 = h / REP;

#pragma unroll
        for (int i = 0; i < 16; i++) {
            int idx = tid + 256 * i;
            int rr = idx >> 5;
            int c4 = (idx & 31) * 4;
            *(float4*)&Qs[rr*FA_QST + c4] =
                *(const float4*)&g_qkv[(size_t)(qb*FAQ + rr) * QKVW + h*HD + c4];
        }

        auto load_kv = [&](int kb, int s) {
            const float* Kg = &g_qkv[(size_t)(kb*64) * QKVW + NQ + g0*HD];
            const float* Vg = Kg + NKV;
            unsigned kbase = smem_base + (unsigned)(FA_QSZ + s*FA_KVSZ) * 4u;
            unsigned vbase = kbase + (unsigned)FA_KSZ * 4u;
#pragma unroll
            for (int i = 0; i < 8; i++) {
                int idx = tid + 256 * i;
                int rr = idx >> 5;
                int c4 = (idx & 31) * 4;
                cp_async16(kbase + (unsigned)(rr*FA_QST + c4) * 4u,
                           Kg + (size_t)rr*QKVW + c4);
                cp_async16(vbase + (unsigned)(rr*FA_VST + c4) * 4u,
                           Vg + (size_t)rr*QKVW + c4);
            }
            cp_commit();
        };

        float o[16][4];
#pragma unroll
        for (int nj = 0; nj < 16; nj++)
#pragma unroll
            for (int rr = 0; rr < 4; rr++) o[nj][rr] = 0.f;
        float m0 = -1e30f, m1 = -1e30f, l0 = 0.f, l1 = 0.f;

        const int kb_max = 2*qb + 1;
        load_kv(0, 0);

        for (int kb = 0; kb <= kb_max; kb++) {
            if (kb < kb_max) { load_kv(kb + 1, (kb + 1) & 1); cp_wait1(); }
            else             { cp_wait0(); }
            __syncthreads();

            unsigned sK = smem_base + (unsigned)(FA_QSZ + (kb & 1)*FA_KVSZ) * 4u;
            const float* Vs = smf + FA_QSZ + (kb & 1)*FA_KVSZ + FA_KSZ;

            float s[8][4];
#pragma unroll
            for (int nj = 0; nj < 8; nj++)
#pragma unroll
                for (int rr = 0; rr < 4; rr++) s[nj][rr] = 0.f;

#pragma unroll
            for (int ks = 0; ks < 16; ks++) {
                int k0 = ks * 8;
                uint4 a, bp[4];
                ldsm_x4(a, smem_base + (unsigned)(a_row*FA_QST + k0 + a_col4)*4u);
#pragma unroll
                for (int p = 0; p < 4; p++)
                    ldsm_x4(bp[p], sK + (unsigned)((b_row + p*16)*FA_QST
                                                   + k0 + b_col4)*4u);
#pragma unroll
                for (int p = 0; p < 4; p++) {
                    mma_tf32(s[2*p  ], a, bp[p].x, bp[p].y);
                    mma_tf32(s[2*p+1], a, bp[p].z, bp[p].w);
                }
            }

            if (kb >= 2*qb) {
                int r0 = qb*FAQ + w16 + g, r1 = r0 + 8;
                int cb0 = kb*64 + 2*t;
#pragma unroll
                for (int nj = 0; nj < 8; nj++) {
                    int c0 = cb0 + nj*8, c1 = c0 + 1;
                    if (c0 > r0) s[nj][0] = -1e30f;
                    if (c1 > r0) s[nj][1] = -1e30f;
                    if (c0 > r1) s[nj][2] = -1e30f;
                    if (c1 > r1) s[nj][3] = -1e30f;
                }
            }

            float mx0 = -1e30f, mx1 = -1e30f;
#pragma unroll
            for (int nj = 0; nj < 8; nj++) {
                mx0 = fmaxf(mx0, fmaxf(s[nj][0], s[nj][1]));
                mx1 = fmaxf(mx1, fmaxf(s[nj][2], s[nj][3]));
            }
            mx0 = fmaxf(mx0, __shfl_xor_sync(0xffffffffu, mx0, 1));
            mx0 = fmaxf(mx0, __shfl_xor_sync(0xffffffffu, mx0, 2));
            mx1 = fmaxf(mx1, __shfl_xor_sync(0xffffffffu, mx1, 1));
            mx1 = fmaxf(mx1, __shfl_xor_sync(0xffffffffu, mx1, 2));
            float mn0 = fmaxf(m0, mx0), mn1 = fmaxf(m1, mx1);
            float al0 = __expf(m0 - mn0), al1 = __expf(m1 - mn1);
            m0 = mn0; m1 = mn1;

            float rs0 = 0.f, rs1 = 0.f;
#pragma unroll
            for (int nj = 0; nj < 8; nj++) {
                s[nj][0] = __expf(s[nj][0] - mn0);
                s[nj][1] = __expf(s[nj][1] - mn0);
                s[nj][2] = __expf(s[nj][2] - mn1);
                s[nj][3] = __expf(s[nj][3] - mn1);
                rs0 += s[nj][0] + s[nj][1];
                rs1 += s[nj][2] + s[nj][3];
            }
            rs0 += __shfl_xor_sync(0xffffffffu, rs0, 1);
            rs0 += __shfl_xor_sync(0xffffffffu, rs0, 2);
            rs1 += __shfl_xor_sync(0xffffffffu, rs1, 1);
            rs1 += __shfl_xor_sync(0xffffffffu, rs1, 2);
            l0 = l0 * al0 + rs0;
            l1 = l1 * al1 + rs1;

#pragma unroll
            for (int nj = 0; nj < 16; nj++) {
                o[nj][0] *= al0; o[nj][1] *= al0;
                o[nj][2] *= al1; o[nj][3] *= al1;
            }

            int src0 = (lane & ~3) + (t >> 1);
            int src1 = src0 + 2;
#pragma unroll
            for (int kt = 0; kt < 8; kt++) {
                float p00 = __shfl_sync(0xffffffffu, s[kt][0], src0);
                float p01 = __shfl_sync(0xffffffffu, s[kt][1], src0);
                float p20 = __shfl_sync(0xffffffffu, s[kt][2], src0);
                float p21 = __shfl_sync(0xffffffffu, s[kt][3], src0);
                float q00 = __shfl_sync(0xffffffffu, s[kt][0], src1);
                float q01 = __shfl_sync(0xffffffffu, s[kt][1], src1);
                float q20 = __shfl_sync(0xffffffffu, s[kt][2], src1);
                float q21 = __shfl_sync(0xffffffffu, s[kt][3], src1);
                uint4 a;
                a.x = f2tf((t & 1) ? p01 : p00);
                a.y = f2tf((t & 1) ? p21 : p20);
                a.z = f2tf((t & 1) ? q01 : q00);
                a.w = f2tf((t & 1) ? q21 : q20);
#pragma unroll
                for (int nj = 0; nj < 16; nj++) {
                    unsigned b0 = __float_as_uint(Vs[(kt*8 + t    )*FA_VST + nj*8 + g]);
                    unsigned b1 = __float_as_uint(Vs[(kt*8 + t + 4)*FA_VST + nj*8 + g]);
                    mma_tf32(o[nj], a, b0, b1);
                }
            }
            __syncthreads();
        }

        float il0 = 1.0f / l0, il1 = 1.0f / l1;
#pragma unroll
        for (int nj = 0; nj < 16; nj++) {
            int row0 = qb*FAQ + w16 + g;
            int col  = h*HD + nj*8 + 2*t;
            float2 v0 = make_float2(__uint_as_float(f2tf(o[nj][0]*il0)),
                                    __uint_as_float(f2tf(o[nj][1]*il0)));
            float2 v1 = make_float2(__uint_as_float(f2tf(o[nj][2]*il1)),
                                    __uint_as_float(f2tf(o[nj][3]*il1)));
            *(float2*)&att[(size_t)row0 * NQ + col]       = v0;
            *(float2*)&att[(size_t)(row0 + 8) * NQ + col] = v1;
        }
    }
}

// ---------------------------------------------------------------------------
extern "C" void kernel_launch(void* const* d_in, const int* in_sizes, int n_in,
                              void* d_out, int out_size)
{
    const float* x  = (const float*)d_in[0];
    const float* wq = (const float*)d_in[1];
    const float* wk = (const float*)d_in[2];
    const float* wv = (const float*)d_in[3];
    const float* wo = (const float*)d_in[4];
    const float* cs = (const float*)d_in[5];
    const float* sn = (const float*)d_in[6];
    float* out = (float*)d_out;

    float *qkv, *att, *xr, *wqkv, *wor;
    cudaGetSymbolAddress((void**)&qkv,  g_qkv);
    cudaGetSymbolAddress((void**)&att,  g_att);
    cudaGetSymbolAddress((void**)&xr,   g_xr);
    cudaGetSymbolAddress((void**)&wqkv, g_wqkv);
    cudaGetSymbolAddress((void**)&wor,  g_wor);

    static bool attr_set = false;
    if (!attr_set) {
        cudaFuncSetAttribute(qkv_gemm_kernel,
            cudaFuncAttributeMaxDynamicSharedMemorySize, QKV_SMEM);
        cudaFuncSetAttribute(oproj_gemm_kernel,
            cudaFuncAttributeMaxDynamicSharedMemorySize, OPJ_SMEM);
        cudaFuncSetAttribute(fa_tc_kernel,
            cudaFuncAttributeMaxDynamicSharedMemorySize, FA_SMEM);
        attr_set = true;
    }

    // Pre-round all GEMM inputs to tf32 (weights packed into g_wqkv)
    round_all_kernel<<<(R_TOT + 255)/256, 256>>>(
        x, wq, wk, wv, wo, xr, wqkv, wor);

    // Packed QKV projection: one 2048x3072x2048 GEMM, 128 CTAs single wave
    qkv_gemm_kernel<<<dim3(QKVW/384, TT/128), 256, QKV_SMEM>>>(xr, wqkv, qkv);

    // Fused RoPE over Q and K (rounds to tf32; Q gets 1/sqrt(HD) folded in)
    const float scale = 0.08838834764831845f;  // 128^-0.5
    rope_fused_kernel<<<(TT*20*64)/256, 256>>>(qkv, cs, sn, scale);

    // Flash attention: 128 persistent CTAs, snake-balanced
    fa_tc_kernel<<<dim3(FA_ITEMS/2, 1), 256, FA_SMEM>>>(att);

    // Output projection: 128 CTAs single wave
    oproj_gemm_kernel<<<dim3(DIMD/256, TT/128), 256, OPJ_SMEM>>>(att, wor, out);
}

// round 8
// speedup vs baseline: 1.0294x; 1.0256x over previous
#include <cuda_runtime.h>
#include <math.h>
#include <stdint.h>

#define TT 2048
#define DIMD 2048
#define NH 16
#define NKVH 4
#define HD 128
#define NQ (NH*HD)     // 2048
#define NKV (NKVH*HD)  // 512
#define REP (NH/NKVH)  // 4
#define QKVW 3072      // packed qkv width

// Scratch (device globals; allocation in kernel_launch is forbidden)
__device__ float g_qkv[TT*QKVW];     // [T][3072]: Q | K | V
__device__ float g_att[TT*NQ];
__device__ float g_xr  [TT*DIMD];
__device__ float g_wqkv[QKVW*DIMD];  // rows: wq(2048) | wk(512) | wv(512)
__device__ float g_wor [DIMD*NQ];

// ---------------------------------------------------------------------------
// helpers
// ---------------------------------------------------------------------------
__device__ __forceinline__ unsigned f2tf(float f) {
    unsigned u; asm("cvt.rna.tf32.f32 %0, %1;" : "=r"(u) : "f"(f)); return u;
}

#define R_X   (TT*DIMD/4)
#define R_WQ  (NQ*DIMD/4)
#define R_WKV (NKV*DIMD/4)
#define R_TOT (R_X + R_WQ + 2*R_WKV + NQ*DIMD/4)

__global__ void round_all_kernel(const float* __restrict__ x,
                                 const float* __restrict__ wq,
                                 const float* __restrict__ wk,
                                 const float* __restrict__ wv,
                                 const float* __restrict__ wo,
                                 float* __restrict__ xr,
                                 float* __restrict__ wqkv,
                                 float* __restrict__ wor)
{
    int i = blockIdx.x * blockDim.x + threadIdx.x;
    if (i >= R_TOT) return;
    const float* in; float* out; int j = i;
    if (j < R_X)                   { in = x;  out = xr; }
    else if ((j -= R_X)   < R_WQ)  { in = wq; out = wqkv; }
    else if ((j -= R_WQ)  < R_WKV) { in = wk; out = wqkv + (size_t)NQ*DIMD; }
    else if ((j -= R_WKV) < R_WKV) { in = wv; out = wqkv + (size_t)(NQ+NKV)*DIMD; }
    else { j -= R_WKV;               in = wo; out = wor; }
    float4 v = ((const float4*)in)[j];
    uint4 o;
    o.x = f2tf(v.x); o.y = f2tf(v.y); o.z = f2tf(v.z); o.w = f2tf(v.w);
    ((uint4*)out)[j] = o;
}

__device__ __forceinline__ void cp_async16(unsigned saddr, const void* g) {
    asm volatile("cp.async.cg.shared.global [%0], [%1], 16;\n"
                 :: "r"(saddr), "l"(g));
}
__device__ __forceinline__ void cp_commit() {
    asm volatile("cp.async.commit_group;\n");
}
__device__ __forceinline__ void cp_wait0() {
    asm volatile("cp.async.wait_group 0;\n");
}
__device__ __forceinline__ void cp_wait1() {
    asm volatile("cp.async.wait_group 1;\n");
}

__device__ __forceinline__ void mma_tf32(float c[4], const uint4& a,
                                         unsigned b0, unsigned b1) {
    asm volatile(
        "mma.sync.aligned.m16n8k8.row.col.f32.tf32.tf32.f32 "
        "{%0,%1,%2,%3}, {%4,%5,%6,%7}, {%8,%9}, {%0,%1,%2,%3};\n"
        : "+f"(c[0]), "+f"(c[1]), "+f"(c[2]), "+f"(c[3])
        : "r"(a.x), "r"(a.y), "r"(a.z), "r"(a.w), "r"(b0), "r"(b1));
}

__device__ __forceinline__ void ldsm_x4(uint4& d, unsigned addr) {
    asm volatile(
        "ldmatrix.sync.aligned.m8n8.x4.shared.b16 {%0,%1,%2,%3}, [%4];\n"
        : "=r"(d.x), "=r"(d.y), "=r"(d.z), "=r"(d.w) : "r"(addr));
}

// ---------------------------------------------------------------------------
// Tensor-core tf32 GEMM: C[2048,N] = A[2048,2048] * B[N,2048]^T.
// CTA tile 128 x NT, 256 threads (8 warps 2m x 4n), warp tile 64 x (NT/4).
// BK=32, 3-stage cp.async ring, ONE barrier per k-iter, a-frag double buffer.
// Columns >= rt_col rounded to tf32 on output.
// ---------------------------------------------------------------------------
#define BKK 32
#define SAST 36
#define GK 2048

template <int NT>
__device__ __forceinline__ void gemm_tc(
    const float* __restrict__ A, const float* __restrict__ B,
    float* __restrict__ C, int N, int bm, int bn, int rt_col)
{
    constexpr int WN  = NT / 4;          // warp n width (96 or 64)
    constexpr int PB  = WN / 16;         // b ldsm per ks (6 or 4)
    constexpr int PBH = PB / 2;          // per half (3 or 2)
    constexpr int ASZ = 128 * SAST;
    constexpr int BSZ = NT * SAST;
    constexpr int STG = ASZ + BSZ;

    extern __shared__ float smf[];
    int tid = threadIdx.x;
    int lane = tid & 31, wid = tid >> 5;
    int wm = (wid & 1) * 64;
    int wn = (wid >> 1) * WN;
    int g = lane >> 2, t = lane & 3;

    int lrow = lane & 7;
    int am   = lane >> 3;
    int a_row  = wm + ((am & 1) << 3) + lrow;
    int a_col4 = (am >> 1) << 2;
    int b_row  = wn + ((am >> 1) << 3) + lrow;
    int b_col4 = (am & 1) << 2;

    unsigned smem_base = (unsigned)__cvta_generic_to_shared(smf);

    float c[4][2*PB][4];
#pragma unroll
    for (int mi = 0; mi < 4; mi++)
#pragma unroll
        for (int nj = 0; nj < 2*PB; nj++)
#pragma unroll
            for (int r = 0; r < 4; r++) c[mi][nj][r] = 0.f;

    auto load_stage = [&](int s, int kt) {
        int k0 = kt * BKK;
        unsigned sa = smem_base + (unsigned)(s * STG) * 4u;
        unsigned sb = sa + (unsigned)ASZ * 4u;
#pragma unroll
        for (int i = 0; i < 4; i++) {                 // A: 128x32
            int idx = tid + 256 * i;
            int row = idx >> 3;
            int kc  = (idx & 7) * 4;
            cp_async16(sa + (unsigned)(row * SAST + kc) * 4u,
                       &A[(size_t)(bm + row) * GK + k0 + kc]);
        }
#pragma unroll
        for (int i = 0; i < NT/32; i++) {             // B: NTx32
            int idx = tid + 256 * i;
            int row = idx >> 3;
            int kc  = (idx & 7) * 4;
            cp_async16(sb + (unsigned)(row * SAST + kc) * 4u,
                       &B[(size_t)(bn + row) * GK + k0 + kc]);
        }
        cp_commit();
    };

    load_stage(0, 0);
    load_stage(1, 1);
    const int KT = GK / BKK;

    int st = 0;   // stage index = kt % 3
    for (int kt = 0; kt < KT; kt++) {
        if (kt + 1 < KT) cp_wait1(); else cp_wait0();
        __syncthreads();
        // safe to overwrite stage (kt+2)%3: all warps passed the barrier,
        // so no one is still reading it (it was stage kt-1).
        if (kt + 2 < KT) {
            int s2 = st + 2; if (s2 >= 3) s2 -= 3;
            load_stage(s2, kt + 2);
        }

        unsigned sA = smem_base + (unsigned)(st * STG) * 4u;
        unsigned sB = sA + (unsigned)ASZ * 4u;

        // a-frag double buffer: preload ks=0
        uint4 a[2][4];
#pragma unroll
        for (int mi = 0; mi < 4; mi++)
            ldsm_x4(a[0][mi], sA + (unsigned)((a_row + mi*16) * SAST
                                              + 0 + a_col4) * 4u);
#pragma unroll
        for (int ks = 0; ks < 4; ks++) {
            int cur = ks & 1;
            int k0 = ks * 8;
            if (ks < 3) {
                int kn = k0 + 8;
#pragma unroll
                for (int mi = 0; mi < 4; mi++)
                    ldsm_x4(a[cur ^ 1][mi],
                            sA + (unsigned)((a_row + mi*16) * SAST
                                            + kn + a_col4) * 4u);
            }
#pragma unroll
            for (int ph = 0; ph < 2; ph++) {
                uint4 bp[PBH];
#pragma unroll
                for (int p2 = 0; p2 < PBH; p2++)
                    ldsm_x4(bp[p2],
                        sB + (unsigned)((b_row + (ph*PBH + p2)*16) * SAST
                                        + k0 + b_col4) * 4u);
#pragma unroll
                for (int mi = 0; mi < 4; mi++)
#pragma unroll
                    for (int p2 = 0; p2 < PBH; p2++) {
                        int p = ph*PBH + p2;
                        mma_tf32(c[mi][2*p  ], a[cur][mi], bp[p2].x, bp[p2].y);
                        mma_tf32(c[mi][2*p+1], a[cur][mi], bp[p2].z, bp[p2].w);
                    }
            }
        }
        if (++st == 3) st = 0;
    }

#pragma unroll
    for (int mi = 0; mi < 4; mi++) {
#pragma unroll
        for (int nj = 0; nj < 2*PB; nj++) {
            int row0 = bm + wm + mi * 16 + g;
            int col  = bn + wn + nj * 8 + 2 * t;
            float v0 = c[mi][nj][0], v1 = c[mi][nj][1];
            float v2 = c[mi][nj][2], v3 = c[mi][nj][3];
            if (col >= rt_col) {
                v0 = __uint_as_float(f2tf(v0)); v1 = __uint_as_float(f2tf(v1));
                v2 = __uint_as_float(f2tf(v2)); v3 = __uint_as_float(f2tf(v3));
            }
            *(float2*)&C[(size_t)row0 * N + col]       = make_float2(v0, v1);
            *(float2*)&C[(size_t)(row0 + 8) * N + col] = make_float2(v2, v3);
        }
    }
}

#define QKV_SMEM (3*(128+384)*SAST*4)   // 221184
#define OPJ_SMEM (3*(128+256)*SAST*4)   // 165888

// Packed QKV projection: grid (8, 16). V columns (>=2560) rounded to tf32.
__global__ __launch_bounds__(256, 1) void qkv_gemm_kernel(
    const float* __restrict__ A, const float* __restrict__ B,
    float* __restrict__ C)
{
    gemm_tc<384>(A, B, C, QKVW, blockIdx.y * 128, blockIdx.x * 384,
                 NQ + NKV /* 2560 */);
}

// Output projection: grid (8, 16).
__global__ __launch_bounds__(256, 1) void oproj_gemm_kernel(
    const float* __restrict__ A, const float* __restrict__ B,
    float* __restrict__ C)
{
    gemm_tc<256>(A, B, C, DIMD, blockIdx.y * 128, blockIdx.x * 256,
                 0x40000000);
}

// ---------------------------------------------------------------------------
// Fused RoPE over Q (16 heads, scaled) and K (4 heads) in packed g_qkv.
// ---------------------------------------------------------------------------
__global__ void rope_fused_kernel(float* __restrict__ qkv,
                                  const float* __restrict__ cs,
                                  const float* __restrict__ sn, float qscale)
{
    int idx = blockIdx.x * blockDim.x + threadIdx.x;  // TT*20*64 threads
    int i  = idx & 63;
    int hh = (idx >> 6) % 20;
    int t  = idx / (64 * 20);
    if (t >= TT) return;
    float c = cs[t * HD + i];
    float s = sn[t * HD + i];
    float* p;
    float scale;
    if (hh < NH) { p = qkv + (size_t)t * QKVW + hh * HD;            scale = qscale; }
    else         { p = qkv + (size_t)t * QKVW + NQ + (hh - NH) * HD; scale = 1.0f; }
    float u1 = p[i], u2 = p[i + 64];
    p[i]      = __uint_as_float(f2tf((u1 * c - u2 * s) * scale));
    p[i + 64] = __uint_as_float(f2tf((u2 * c + u1 * s) * scale));
}

// ---------------------------------------------------------------------------
// Tensor-core flash attention (tf32, legacy mma). BQ=128, BKV=64, 256 thr.
// Persistent snake: 128 CTAs, CTA b handles items b and 255-b (balanced).
// QK fragment double-buffering + PV software-pipelined V loads.
// ---------------------------------------------------------------------------
#define FAQ 128
#define FA_QST 132
#define FA_VST 136
#define FA_QSZ (FAQ*FA_QST)
#define FA_KSZ (64*FA_QST)
#define FA_KVSZ (FA_KSZ + 64*FA_VST)
#define FA_SMEM ((FA_QSZ + 2*FA_KVSZ)*4)
#define FA_ITEMS (NH * (TT/FAQ))   // 256

__global__ __launch_bounds__(256, 1) void fa_tc_kernel(float* __restrict__ att)
{
    extern __shared__ float smf[];
    int tid = threadIdx.x;
    int lane = tid & 31, wid = tid >> 5;
    int g = lane >> 2, t = lane & 3;
    int w16 = wid * 16;

    int lrow = lane & 7;
    int am   = lane >> 3;
    int a_row  = w16 + ((am & 1) << 3) + lrow;
    int a_col4 = (am >> 1) << 2;
    int b_row  = ((am >> 1) << 3) + lrow;
    int b_col4 = (am & 1) << 2;

    unsigned smem_base = (unsigned)__cvta_generic_to_shared(smf);
    float* Qs = smf;

#pragma unroll 1
    for (int pass = 0; pass < 2; pass++) {
        int r = pass == 0 ? (int)blockIdx.x : (FA_ITEMS - 1 - (int)blockIdx.x);
        int qb = (TT/FAQ) - 1 - (r >> 4);
        int h  = r & 15;
        int g0 = h / REP;

#pragma unroll
        for (int i = 0; i < 16; i++) {
            int idx = tid + 256 * i;
            int rr = idx >> 5;
            int c4 = (idx & 31) * 4;
            *(float4*)&Qs[rr*FA_QST + c4] =
                *(const float4*)&g_qkv[(size_t)(qb*FAQ + rr) * QKVW + h*HD + c4];
        }

        auto load_kv = [&](int kb, int s) {
            const float* Kg = &g_qkv[(size_t)(kb*64) * QKVW + NQ + g0*HD];
            const float* Vg = Kg + NKV;
            unsigned kbase = smem_base + (unsigned)(FA_QSZ + s*FA_KVSZ) * 4u;
            unsigned vbase = kbase + (unsigned)FA_KSZ * 4u;
#pragma unroll
            for (int i = 0; i < 8; i++) {
                int idx = tid + 256 * i;
                int rr = idx >> 5;
                int c4 = (idx & 31) * 4;
                cp_async16(kbase + (unsigned)(rr*FA_QST + c4) * 4u,
                           Kg + (size_t)rr*QKVW + c4);
                cp_async16(vbase + (unsigned)(rr*FA_VST + c4) * 4u,
                           Vg + (size_t)rr*QKVW + c4);
            }
            cp_commit();
        };

        float o[16][4];
#pragma unroll
        for (int nj = 0; nj < 16; nj++)
#pragma unroll
            for (int rr = 0; rr < 4; rr++) o[nj][rr] = 0.f;
        float m0 = -1e30f, m1 = -1e30f, l0 = 0.f, l1 = 0.f;

        const int kb_max = 2*qb + 1;
        load_kv(0, 0);

        for (int kb = 0; kb <= kb_max; kb++) {
            if (kb < kb_max) { load_kv(kb + 1, (kb + 1) & 1); cp_wait1(); }
            else             { cp_wait0(); }
            __syncthreads();

            unsigned sK = smem_base + (unsigned)(FA_QSZ + (kb & 1)*FA_KVSZ) * 4u;
            const float* Vs = smf + FA_QSZ + (kb & 1)*FA_KVSZ + FA_KSZ;

            float s[8][4];
#pragma unroll
            for (int nj = 0; nj < 8; nj++)
#pragma unroll
                for (int rr = 0; rr < 4; rr++) s[nj][rr] = 0.f;

            // ---- S = Q K^T with fragment double buffering ----
            uint4 a2[2], bp2[2][4];
            ldsm_x4(a2[0], smem_base + (unsigned)(a_row*FA_QST + a_col4)*4u);
#pragma unroll
            for (int p = 0; p < 4; p++)
                ldsm_x4(bp2[0][p], sK + (unsigned)((b_row + p*16)*FA_QST
                                                   + b_col4)*4u);
#pragma unroll
            for (int ks = 0; ks < 16; ks++) {
                int cur = ks & 1;
                if (ks < 15) {
                    int kn = (ks + 1) * 8;
                    ldsm_x4(a2[cur ^ 1],
                            smem_base + (unsigned)(a_row*FA_QST + kn + a_col4)*4u);
#pragma unroll
                    for (int p = 0; p < 4; p++)
                        ldsm_x4(bp2[cur ^ 1][p],
                                sK + (unsigned)((b_row + p*16)*FA_QST
                                                + kn + b_col4)*4u);
                }
#pragma unroll
                for (int p = 0; p < 4; p++) {
                    mma_tf32(s[2*p  ], a2[cur], bp2[cur][p].x, bp2[cur][p].y);
                    mma_tf32(s[2*p+1], a2[cur], bp2[cur][p].z, bp2[cur][p].w);
                }
            }

            if (kb >= 2*qb) {
                int r0 = qb*FAQ + w16 + g, r1 = r0 + 8;
                int cb0 = kb*64 + 2*t;
#pragma unroll
                for (int nj = 0; nj < 8; nj++) {
                    int c0 = cb0 + nj*8, c1 = c0 + 1;
                    if (c0 > r0) s[nj][0] = -1e30f;
                    if (c1 > r0) s[nj][1] = -1e30f;
                    if (c0 > r1) s[nj][2] = -1e30f;
                    if (c1 > r1) s[nj][3] = -1e30f;
                }
            }

            float mx0 = -1e30f, mx1 = -1e30f;
#pragma unroll
            for (int nj = 0; nj < 8; nj++) {
                mx0 = fmaxf(mx0, fmaxf(s[nj][0], s[nj][1]));
                mx1 = fmaxf(mx1, fmaxf(s[nj][2], s[nj][3]));
            }
            mx0 = fmaxf(mx0, __shfl_xor_sync(0xffffffffu, mx0, 1));
            mx0 = fmaxf(mx0, __shfl_xor_sync(0xffffffffu, mx0, 2));
            mx1 = fmaxf(mx1, __shfl_xor_sync(0xffffffffu, mx1, 1));
            mx1 = fmaxf(mx1, __shfl_xor_sync(0xffffffffu, mx1, 2));
            float mn0 = fmaxf(m0, mx0), mn1 = fmaxf(m1, mx1);
            float al0 = __expf(m0 - mn0), al1 = __expf(m1 - mn1);
            m0 = mn0; m1 = mn1;

            float rs0 = 0.f, rs1 = 0.f;
#pragma unroll
            for (int nj = 0; nj < 8; nj++) {
                s[nj][0] = __expf(s[nj][0] - mn0);
                s[nj][1] = __expf(s[nj][1] - mn0);
                s[nj][2] = __expf(s[nj][2] - mn1);
                s[nj][3] = __expf(s[nj][3] - mn1);
                rs0 += s[nj][0] + s[nj][1];
                rs1 += s[nj][2] + s[nj][3];
            }
            rs0 += __shfl_xor_sync(0xffffffffu, rs0, 1);
            rs0 += __shfl_xor_sync(0xffffffffu, rs0, 2);
            rs1 += __shfl_xor_sync(0xffffffffu, rs1, 1);
            rs1 += __shfl_xor_sync(0xffffffffu, rs1, 2);
            l0 = l0 * al0 + rs0;
            l1 = l1 * al1 + rs1;

#pragma unroll
            for (int nj = 0; nj < 16; nj++) {
                o[nj][0] *= al0; o[nj][1] *= al0;
                o[nj][2] *= al1; o[nj][3] *= al1;
            }

            // ---- O += P @ V with software-pipelined V loads ----
            int src0 = (lane & ~3) + (t >> 1);
            int src1 = src0 + 2;
#pragma unroll
            for (int kt = 0; kt < 8; kt++) {
                // issue first V pair before the shuffle chain
                unsigned vb0 = __float_as_uint(Vs[(kt*8 + t    )*FA_VST + g]);
                unsigned vb1 = __float_as_uint(Vs[(kt*8 + t + 4)*FA_VST + g]);
                float p00 = __shfl_sync(0xffffffffu, s[kt][0], src0);
                float p01 = __shfl_sync(0xffffffffu, s[kt][1], src0);
                float p20 = __shfl_sync(0xffffffffu, s[kt][2], src0);
                float p21 = __shfl_sync(0xffffffffu, s[kt][3], src0);
                float q00 = __shfl_sync(0xffffffffu, s[kt][0], src1);
                float q01 = __shfl_sync(0xffffffffu, s[kt][1], src1);
                float q20 = __shfl_sync(0xffffffffu, s[kt][2], src1);
                float q21 = __shfl_sync(0xffffffffu, s[kt][3], src1);
                uint4 a;
                a.x = f2tf((t & 1) ? p01 : p00);
                a.y = f2tf((t & 1) ? p21 : p20);
                a.z = f2tf((t & 1) ? q01 : q00);
                a.w = f2tf((t & 1) ? q21 : q20);
#pragma unroll
                for (int nj = 0; nj < 16; nj++) {
                    unsigned nb0, nb1;
                    if (nj < 15) {
                        nb0 = __float_as_uint(Vs[(kt*8 + t    )*FA_VST + (nj+1)*8 + g]);
                        nb1 = __float_as_uint(Vs[(kt*8 + t + 4)*FA_VST + (nj+1)*8 + g]);
                    }
                    mma_tf32(o[nj], a, vb0, vb1);
                    if (nj < 15) { vb0 = nb0; vb1 = nb1; }
                }
            }
            __syncthreads();
        }

        float il0 = 1.0f / l0, il1 = 1.0f / l1;
#pragma unroll
        for (int nj = 0; nj < 16; nj++) {
            int row0 = qb*FAQ + w16 + g;
            int col  = h*HD + nj*8 + 2*t;
            float2 v0 = make_float2(__uint_as_float(f2tf(o[nj][0]*il0)),
                                    __uint_as_float(f2tf(o[nj][1]*il0)));
            float2 v1 = make_float2(__uint_as_float(f2tf(o[nj][2]*il1)),
                                    __uint_as_float(f2tf(o[nj][3]*il1)));
            *(float2*)&att[(size_t)row0 * NQ + col]       = v0;
            *(float2*)&att[(size_t)(row0 + 8) * NQ + col] = v1;
        }
    }
}

// ---------------------------------------------------------------------------
extern "C" void kernel_launch(void* const* d_in, const int* in_sizes, int n_in,
                              void* d_out, int out_size)
{
    const float* x  = (const float*)d_in[0];
    const float* wq = (const float*)d_in[1];
    const float* wk = (const float*)d_in[2];
    const float* wv = (const float*)d_in[3];
    const float* wo = (const float*)d_in[4];
    const float* cs = (const float*)d_in[5];
    const float* sn = (const float*)d_in[6];
    float* out = (float*)d_out;

    float *qkv, *att, *xr, *wqkv, *wor;
    cudaGetSymbolAddress((void**)&qkv,  g_qkv);
    cudaGetSymbolAddress((void**)&att,  g_att);
    cudaGetSymbolAddress((void**)&xr,   g_xr);
    cudaGetSymbolAddress((void**)&wqkv, g_wqkv);
    cudaGetSymbolAddress((void**)&wor,  g_wor);

    static bool attr_set = false;
    if (!attr_set) {
        cudaFuncSetAttribute(qkv_gemm_kernel,
            cudaFuncAttributeMaxDynamicSharedMemorySize, QKV_SMEM);
        cudaFuncSetAttribute(oproj_gemm_kernel,
            cudaFuncAttributeMaxDynamicSharedMemorySize, OPJ_SMEM);
        cudaFuncSetAttribute(fa_tc_kernel,
            cudaFuncAttributeMaxDynamicSharedMemorySize, FA_SMEM);
        attr_set = true;
    }

    // Pre-round all GEMM inputs to tf32 (weights packed into g_wqkv)
    round_all_kernel<<<(R_TOT + 255)/256, 256>>>(
        x, wq, wk, wv, wo, xr, wqkv, wor);

    // Packed QKV projection: one 2048x3072x2048 GEMM, 128 CTAs single wave
    qkv_gemm_kernel<<<dim3(QKVW/384, TT/128), 256, QKV_SMEM>>>(xr, wqkv, qkv);

    // Fused RoPE over Q and K (rounds to tf32; Q gets 1/sqrt(HD) folded in)
    const float scale = 0.08838834764831845f;  // 128^-0.5
    rope_fused_kernel<<<(TT*20*64)/256, 256>>>(qkv, cs, sn, scale);

    // Flash attention: 128 persistent CTAs, snake-balanced
    fa_tc_kernel<<<dim3(FA_ITEMS/2, 1), 256, FA_SMEM>>>(att);

    // Output projection: 128 CTAs single wave
    oproj_gemm_kernel<<<dim3(DIMD/256, TT/128), 256, OPJ_SMEM>>>(att, wor, out);
}